// round 15
// baseline (speedup 1.0000x reference)
#include <cuda_runtime.h>
#include <cuda_fp16.h>
#include <stdint.h>

// CosRec fused kernel — fp16 mma.sync (HMMA), round 15.
// Evidence from rounds 6/12/14: throughput scales linearly with resident
// warps/SM (latency-bound), invariant to LDS bytes/instrs. This round raises
// occupancy: grid 1024 (512 rows x 2 m-halves), 128-thread CTAs, smem 43.8KB,
// launch_bounds(128,5) -> 5 CTAs/SM = 20 warps and balanced waves.
// Row halves write partial x to global scratch; a small second kernel
// combines halves + user-emb + W2 dots.

#define THREADS 128
#define TSTR 56            // table row stride (words)
#define TE   40            // E-fragment table row stride (words)

// ---- main-kernel shared memory byte offsets ----
#define OFF_SI     0       // 32 ints (seq idx)                       128 B
#define OFF_RED    128     // fp32 sRedW [4][56] =                    896 B
#define OFF_BFRAG  1024    // uint2 Wf2 bfrags [13][7][32] =        23296 B
#define OFF_A2     24320   // uint32 A-table [32][56] =              7168 B
#define OFF_B2     31488   // uint32 B-table [32][56] =              7168 B
#define OFF_E2     38656   // uint32 E-table [32][40] =              5120 B
#define SMEM_TOTAL 43776   // -> 5 CTAs/SM (219 KB of 228 KB)

__device__ float gX[512 * 2 * 104];   // per (row, m-half) partial x

__device__ __forceinline__ void mma16816(float* d, uint32_t a0, uint32_t a1,
                                         uint32_t a2, uint32_t a3,
                                         uint32_t b0, uint32_t b1) {
    asm volatile(
        "mma.sync.aligned.m16n8k16.row.col.f32.f16.f16.f32 "
        "{%0,%1,%2,%3}, {%4,%5,%6,%7}, {%8,%9}, {%0,%1,%2,%3};"
        : "+f"(d[0]), "+f"(d[1]), "+f"(d[2]), "+f"(d[3])
        : "r"(a0), "r"(a1), "r"(a2), "r"(a3), "r"(b0), "r"(b1));
}
__device__ __forceinline__ void mma16816_init(float* d, uint32_t a0, uint32_t a1,
                                              uint32_t a2, uint32_t a3,
                                              uint32_t b0, uint32_t b1) {
    asm volatile(
        "mma.sync.aligned.m16n8k16.row.col.f32.f16.f16.f32 "
        "{%0,%1,%2,%3}, {%4,%5,%6,%7}, {%8,%9}, {%10,%11,%12,%13};"
        : "=f"(d[0]), "=f"(d[1]), "=f"(d[2]), "=f"(d[3])
        : "r"(a0), "r"(a1), "r"(a2), "r"(a3), "r"(b0), "r"(b1),
          "f"(0.0f), "f"(0.0f), "f"(0.0f), "f"(0.0f));
}

__device__ __forceinline__ uint32_t hbuild(uint32_t a, uint32_t b) {
    __half2 av = *reinterpret_cast<__half2*>(&a);
    __half2 bv = *reinterpret_cast<__half2*>(&b);
    __half2 r  = __hmax2(__hadd2(av, bv), __float2half2_rn(0.0f));
    return *reinterpret_cast<uint32_t*>(&r);
}
__device__ __forceinline__ uint32_t h2bits(__half2 v) {
    return *reinterpret_cast<uint32_t*>(&v);
}
// paired slot: (k2, k2+4) adjacent -> slot = blk + (k2&3)*2 + ((k2>>2)&1)
__device__ __forceinline__ int pslot(int kk) {
    return (kk & ~7) + ((kk & 3) << 1) + ((kk >> 2) & 1);
}

// Mainloop for one warp: 8 a-blocks of 32 pairs (2 m-tiles per bfrag load),
// NT n-tiles starting at NTB. xacc[2*NT] accumulates relu'd column sums.
template<int NT, int NTB>
__device__ __forceinline__ void run_mainloop(
    const uint32_t* __restrict__ uA2, const uint32_t* __restrict__ uB2,
    const uint2* __restrict__ bfragW,
    int aBase, int gid, int tig, int lane, float* xacc)
{
    const int cA0 = gid, cB0 = gid + 8, cA1 = gid + 16, cB1 = gid + 24;
    for (int j = 0; j < 8; ++j) {
        const int aI = aBase + j;
        float acc[2][NT][4];
        #pragma unroll
        for (int ks = 0; ks < 7; ++ks) {
            const int so = ks * 8 + tig * 2;
            uint2 Bab = *(const uint2*)&uB2[aI  * TSTR + so];
            uint2 Aa0 = *(const uint2*)&uA2[cA0 * TSTR + so];
            uint2 Ab0 = *(const uint2*)&uA2[cB0 * TSTR + so];
            uint2 Aa1 = *(const uint2*)&uA2[cA1 * TSTR + so];
            uint2 Ab1 = *(const uint2*)&uA2[cB1 * TSTR + so];
            uint32_t a00 = hbuild(Aa0.x, Bab.x), a01 = hbuild(Ab0.x, Bab.x);
            uint32_t a02 = hbuild(Aa0.y, Bab.y), a03 = hbuild(Ab0.y, Bab.y);
            uint32_t a10 = hbuild(Aa1.x, Bab.x), a11 = hbuild(Ab1.x, Bab.x);
            uint32_t a12 = hbuild(Aa1.y, Bab.y), a13 = hbuild(Ab1.y, Bab.y);
            #pragma unroll
            for (int q = 0; q < NT; ++q) {
                uint2 bb = bfragW[((NTB + q) * 7 + ks) * 32 + lane];
                if (ks == 0) {
                    mma16816_init(acc[0][q], a00, a01, a02, a03, bb.x, bb.y);
                    mma16816_init(acc[1][q], a10, a11, a12, a13, bb.x, bb.y);
                } else {
                    mma16816(acc[0][q], a00, a01, a02, a03, bb.x, bb.y);
                    mma16816(acc[1][q], a10, a11, a12, a13, bb.x, bb.y);
                }
            }
        }
        #pragma unroll
        for (int q = 0; q < NT; ++q) {
            xacc[q * 2]     += fmaxf(acc[0][q][0], 0.0f) + fmaxf(acc[0][q][2], 0.0f)
                             + fmaxf(acc[1][q][0], 0.0f) + fmaxf(acc[1][q][2], 0.0f);
            xacc[q * 2 + 1] += fmaxf(acc[0][q][1], 0.0f) + fmaxf(acc[0][q][3], 0.0f)
                             + fmaxf(acc[1][q][1], 0.0f) + fmaxf(acc[1][q][3], 0.0f);
        }
    }
}

__global__ __launch_bounds__(THREADS, 5)
void cosrec_main(
    const int*   __restrict__ seq_var,   // [512*32]
    const float* __restrict__ item_emb,  // [100000*64]
    const float* __restrict__ W1,        // [100*128]
    const float* __restrict__ b1,        // [100]
    const float* __restrict__ Wf2,       // [100*100]
    const float* __restrict__ bf2)       // [100]
{
    extern __shared__ char smem[];
    int*      sI     = (int*)(smem + OFF_SI);
    float*    sRedW  = (float*)(smem + OFF_RED);
    uint2*    bfragW = (uint2*)(smem + OFF_BFRAG);
    uint32_t* uA2    = (uint32_t*)(smem + OFF_A2);
    uint32_t* uB2    = (uint32_t*)(smem + OFF_B2);
    uint32_t* uE2    = (uint32_t*)(smem + OFF_E2);

    const int row  = blockIdx.x >> 1;
    const int mh   = blockIdx.x & 1;     // m-half: a in [mh*16, mh*16+16)
    const int tid  = threadIdx.x;
    const int wid  = tid >> 5;
    const int lane = tid & 31;
    const int gid  = lane >> 2;
    const int tig  = lane & 3;

    // ---- indices ----
    if (tid < 32) sI[tid] = seq_var[row * 32 + tid];

    // ---- pack Wf2 b-fragments (plain [nt][ks][lane]) ----
    for (int idx = tid; idx < 13 * 7 * 32; idx += THREADS) {
        int nt  = idx / 224;
        int rem = idx - nt * 224;
        int ks  = rem >> 5, ln = rem & 31;
        int n   = nt * 8 + (ln >> 2);
        int k0  = ks * 16 + (ln & 3) * 2;
        float w0, w1, w2v, w3v;
        if (n < 100) {
            const float* wr = Wf2 + n * 100;
            w0  = (k0     < 100) ? wr[k0]     : ((k0     == 100) ? bf2[n] : 0.0f);
            w1  = (k0 + 1 < 100) ? wr[k0 + 1] : ((k0 + 1 == 100) ? bf2[n] : 0.0f);
            w2v = (k0 + 8 < 100) ? wr[k0 + 8] : ((k0 + 8 == 100) ? bf2[n] : 0.0f);
            w3v = (k0 + 9 < 100) ? wr[k0 + 9] : ((k0 + 9 == 100) ? bf2[n] : 0.0f);
        } else {
            w0 = w1 = w2v = w3v = 0.0f;
        }
        uint2 val;
        val.x = h2bits(__floats2half2_rn(w0, w1));
        val.y = h2bits(__floats2half2_rn(w2v, w3v));
        bfragW[idx] = val;
    }
    __syncthreads();

    // ---- gather E as fp16 fragment table [l][pslot(d2)] ----
    for (int idx = tid; idx < 32 * 40; idx += THREADS) {
        int l = idx / 40, d2 = idx - l * 40;
        __half2 v;
        if (d2 < 32) {
            const float* ep = item_emb + (size_t)sI[l] * 64 + 2 * d2;
            v = __floats2half2_rn(ep[0], ep[1]);
        } else if (d2 == 32) {
            v = __floats2half2_rn(1.0f, 0.0f);
        } else {
            v = __float2half2_rn(0.0f);
        }
        uE2[l * TE + pslot(d2)] = h2bits(v);
    }
    // ---- init table slots kk=50..55 (bias col + zero pad) ----
    for (int idx = tid; idx < 32 * 6; idx += THREADS) {
        int c = idx / 6, j = idx - c * 6;
        int s = pslot(50 + j);
        uA2[c * TSTR + s] = (j == 0) ? 0x00003C00u : 0u;  // (1.0h, 0)
        uB2[c * TSTR + s] = 0u;
    }
    __syncthreads();

    // ---- phase 2: A/B via HMMA; W1 b-frags built on the fly from L2 ----
    // 39 combos: cb<26 -> A (p=0, nt=cb>>1, mt=cb&1); else B (p=1, mt=mh).
    for (int cb = wid; cb < 39; cb += 4) {
        int p, nt, mt;
        if (cb < 26) { p = 0; nt = cb >> 1; mt = cb & 1; }
        else         { p = 1; nt = cb - 26; mt = mh; }
        const int c0 = mt * 16 + gid;
        const int f  = nt * 8 + gid;

        float acc[4];
        #pragma unroll
        for (int ks = 0; ks < 5; ++ks) {
            const int so = ks * 8 + tig * 2;
            uint2 Aa = *(const uint2*)&uE2[c0 * TE + so];
            uint2 Ab = *(const uint2*)&uE2[(c0 + 8) * TE + so];
            // W1 fragment on the fly: k in {k0,k0+1,k0+8,k0+9}, k<64 real,
            // p==0 && k==64 -> b1[f], else 0.
            const int k0 = ks * 16 + tig * 2;
            float w[4] = {0.0f, 0.0f, 0.0f, 0.0f};
            if (f < 100) {
                const float* wr = W1 + f * 128 + p * 64;
                const int kk4[4] = {k0, k0 + 1, k0 + 8, k0 + 9};
                #pragma unroll
                for (int q = 0; q < 4; ++q) {
                    int k = kk4[q];
                    if (k < 64)                 w[q] = __ldg(wr + k);
                    else if (p == 0 && k == 64) w[q] = __ldg(b1 + f);
                }
            }
            uint32_t bbx = h2bits(__floats2half2_rn(w[0], w[1]));
            uint32_t bby = h2bits(__floats2half2_rn(w[2], w[3]));
            if (ks == 0) mma16816_init(acc, Aa.x, Ab.x, Aa.y, Ab.y, bbx, bby);
            else         mma16816(acc, Aa.x, Ab.x, Aa.y, Ab.y, bbx, bby);
        }
        const int kk = nt * 4 + tig;
        if (kk < 50) {
            uint32_t* tbl = p ? uB2 : uA2;
            const int s = pslot(kk);
            tbl[c0 * TSTR + s]       = h2bits(__floats2half2_rn(acc[0], acc[1]));
            tbl[(c0 + 8) * TSTR + s] = h2bits(__floats2half2_rn(acc[2], acc[3]));
        }
    }
    __syncthreads();

    // ---- mainloop: warps {0,1} nt 0-6, {2,3} nt 7-12; a split by wid&1 ----
    float xacc[14];
    #pragma unroll
    for (int j = 0; j < 14; ++j) xacc[j] = 0.0f;

    const int aBase = mh * 16 + (wid & 1) * 8;
    if (wid < 2) run_mainloop<7, 0>(uA2, uB2, bfragW, aBase, gid, tig, lane, xacc);
    else         run_mainloop<6, 7>(uA2, uB2, bfragW, aBase, gid, tig, lane, xacc);

    // ---- reduce: shfl, per-warp store, pairwise combine, write gX ----
    #pragma unroll
    for (int j = 0; j < 14; ++j) {
        float s = xacc[j];
        s += __shfl_down_sync(0xffffffffu, s, 16);
        s += __shfl_down_sync(0xffffffffu, s, 8);
        s += __shfl_down_sync(0xffffffffu, s, 4);
        xacc[j] = s;
    }
    if (lane < 4) {
        const int NTL = (wid < 2) ? 7 : 6;
        for (int q = 0; q < NTL; ++q) {
            int n0 = q * 8 + lane * 2;      // lane == tig here
            sRedW[wid * 56 + n0]     = xacc[q * 2];
            sRedW[wid * 56 + n0 + 1] = xacc[q * 2 + 1];
        }
    }
    __syncthreads();
    float* gx = gX + (size_t)(row * 2 + mh) * 104;
    if (tid < 56) {
        gx[tid] = sRedW[tid] + sRedW[56 + tid];
    } else if (tid < 100) {
        int c = tid - 56;
        gx[tid] = sRedW[112 + c] + sRedW[168 + c];
    }
}

// Finalize: x = gX[row][0] + gX[row][1]; append uemb; 3 dot products.
__global__ __launch_bounds__(128)
void cosrec_final(
    const int*   __restrict__ user_var,  // [512]
    const int*   __restrict__ item_var,  // [512*3]
    const float* __restrict__ user_emb,  // [100000*64]
    const float* __restrict__ W2,        // [100000*164]
    const float* __restrict__ b2,        // [100000]
    float*       __restrict__ out)       // [512*3]
{
    __shared__ float sX[164];
    __shared__ int   sIt[4];
    const int row  = blockIdx.x;
    const int tid  = threadIdx.x;
    const int wid  = tid >> 5;
    const int lane = tid & 31;

    const float* gx = gX + (size_t)row * 2 * 104;
    if (tid < 100)       sX[tid] = gx[tid] + gx[104 + tid];
    else if (tid >= 124) sIt[tid - 124] = (tid < 127) ? item_var[row * 3 + tid - 124]
                                                      : user_var[row];
    __syncthreads();
    if (tid < 64) sX[100 + tid] = user_emb[(size_t)sIt[3] * 64 + tid];
    __syncthreads();

    if (wid < 3) {
        int it = sIt[wid];
        const float* w2p = W2 + (size_t)it * 164;
        float s = 0.0f;
        for (int j = lane; j < 164; j += 32) s = fmaf(w2p[j], sX[j], s);
        #pragma unroll
        for (int off = 16; off; off >>= 1)
            s += __shfl_down_sync(0xffffffffu, s, off);
        if (lane == 0) out[row * 3 + wid] = b2[it] + s;
    }
}

extern "C" void kernel_launch(void* const* d_in, const int* in_sizes, int n_in,
                              void* d_out, int out_size) {
    (void)in_sizes; (void)n_in; (void)out_size;
    cudaFuncSetAttribute(cosrec_main,
                         cudaFuncAttributeMaxDynamicSharedMemorySize, SMEM_TOTAL);
    cosrec_main<<<1024, THREADS, SMEM_TOTAL>>>(
        (const int*)d_in[0],    // seq_var
        (const float*)d_in[3],  // item_emb
        (const float*)d_in[7],  // W1
        (const float*)d_in[8],  // b1
        (const float*)d_in[9],  // Wf2
        (const float*)d_in[10]);// bf2
    cosrec_final<<<512, 128>>>(
        (const int*)d_in[1],    // user_var
        (const int*)d_in[2],    // item_var
        (const float*)d_in[4],  // user_emb
        (const float*)d_in[5],  // W2
        (const float*)d_in[6],  // b2
        (float*)d_out);
}

// round 16
// speedup vs baseline: 1.3371x; 1.3371x over previous
#include <cuda_runtime.h>
#include <cuda_fp16.h>
#include <stdint.h>

// CosRec fused kernel — fp16 mma.sync (HMMA), round 16.
// = round 14 internals exactly (127 regs, 2 CTAs/SM, nt-split + 2-m-tile
// mainloop), but ONE batch row per CTA and grid 512: total resident warps
// rise (296 CTAs resident vs 256) and the 1.73-wave schedule load-balances
// (~3.46 rows/SM) instead of leaving 40 SMs half-occupied.

#define THREADS 256
#define TSTR 56            // table row stride (words)
#define TE   40            // E-fragment table row stride (words)

// ---- shared memory byte offsets ----
#define OFF_SI     0       // 36 ints                                  144 B
#define OFF_SX     160     // 164 floats (ends 816)
#define OFF_BFRAG  1024    // uint2 Wf2 bfrags [13][7][32] =         23296 B
#define OFF_A2     24320   // uint32 A-table [32][56] =               7168 B
#define OFF_B2     31488   // uint32 B-table [32][56] =               7168 B
#define OFF_W1F    38656   // uint2 W1 bfrags 2*13*5*32*8 =          33280 B
#define OFF_E2     71936   // uint32 E-table [32][40] =               5120 B
#define OFF_RED    77056   // fp32 sRedW [8][56] =                    1792 B
#define SMEM_TOTAL 78848

__device__ __forceinline__ void mma16816(float* d, uint32_t a0, uint32_t a1,
                                         uint32_t a2, uint32_t a3,
                                         uint32_t b0, uint32_t b1) {
    asm volatile(
        "mma.sync.aligned.m16n8k16.row.col.f32.f16.f16.f32 "
        "{%0,%1,%2,%3}, {%4,%5,%6,%7}, {%8,%9}, {%0,%1,%2,%3};"
        : "+f"(d[0]), "+f"(d[1]), "+f"(d[2]), "+f"(d[3])
        : "r"(a0), "r"(a1), "r"(a2), "r"(a3), "r"(b0), "r"(b1));
}
__device__ __forceinline__ void mma16816_init(float* d, uint32_t a0, uint32_t a1,
                                              uint32_t a2, uint32_t a3,
                                              uint32_t b0, uint32_t b1) {
    asm volatile(
        "mma.sync.aligned.m16n8k16.row.col.f32.f16.f16.f32 "
        "{%0,%1,%2,%3}, {%4,%5,%6,%7}, {%8,%9}, {%10,%11,%12,%13};"
        : "=f"(d[0]), "=f"(d[1]), "=f"(d[2]), "=f"(d[3])
        : "r"(a0), "r"(a1), "r"(a2), "r"(a3), "r"(b0), "r"(b1),
          "f"(0.0f), "f"(0.0f), "f"(0.0f), "f"(0.0f));
}

__device__ __forceinline__ uint32_t hbuild(uint32_t a, uint32_t b) {
    __half2 av = *reinterpret_cast<__half2*>(&a);
    __half2 bv = *reinterpret_cast<__half2*>(&b);
    __half2 r  = __hmax2(__hadd2(av, bv), __float2half2_rn(0.0f));
    return *reinterpret_cast<uint32_t*>(&r);
}
__device__ __forceinline__ uint32_t h2bits(__half2 v) {
    return *reinterpret_cast<uint32_t*>(&v);
}
// paired slot: (k2, k2+4) adjacent -> slot = blk + (k2&3)*2 + ((k2>>2)&1)
__device__ __forceinline__ int pslot(int kk) {
    return (kk & ~7) + ((kk & 3) << 1) + ((kk >> 2) & 1);
}

// Mainloop for one warp: 8 a-blocks of 32 pairs (2 m-tiles per bfrag load),
// NT n-tiles starting at NTB. xacc[2*NT] accumulates relu'd column sums.
template<int NT, int NTB>
__device__ __forceinline__ void run_mainloop(
    const uint32_t* __restrict__ uA2, const uint32_t* __restrict__ uB2,
    const uint2* __restrict__ bfragW,
    int mw, int gid, int tig, int lane, float* xacc)
{
    const int cA0 = gid, cB0 = gid + 8, cA1 = gid + 16, cB1 = gid + 24;
    for (int j = 0; j < 8; ++j) {
        const int aI = mw * 8 + j;       // 32-pair block index == a index
        float acc[2][NT][4];
        #pragma unroll
        for (int ks = 0; ks < 7; ++ks) {
            const int so = ks * 8 + tig * 2;
            uint2 Bab = *(const uint2*)&uB2[aI  * TSTR + so];
            uint2 Aa0 = *(const uint2*)&uA2[cA0 * TSTR + so];
            uint2 Ab0 = *(const uint2*)&uA2[cB0 * TSTR + so];
            uint2 Aa1 = *(const uint2*)&uA2[cA1 * TSTR + so];
            uint2 Ab1 = *(const uint2*)&uA2[cB1 * TSTR + so];
            uint32_t a00 = hbuild(Aa0.x, Bab.x), a01 = hbuild(Ab0.x, Bab.x);
            uint32_t a02 = hbuild(Aa0.y, Bab.y), a03 = hbuild(Ab0.y, Bab.y);
            uint32_t a10 = hbuild(Aa1.x, Bab.x), a11 = hbuild(Ab1.x, Bab.x);
            uint32_t a12 = hbuild(Aa1.y, Bab.y), a13 = hbuild(Ab1.y, Bab.y);
            #pragma unroll
            for (int q = 0; q < NT; ++q) {
                uint2 bb = bfragW[((NTB + q) * 7 + ks) * 32 + lane];
                if (ks == 0) {
                    mma16816_init(acc[0][q], a00, a01, a02, a03, bb.x, bb.y);
                    mma16816_init(acc[1][q], a10, a11, a12, a13, bb.x, bb.y);
                } else {
                    mma16816(acc[0][q], a00, a01, a02, a03, bb.x, bb.y);
                    mma16816(acc[1][q], a10, a11, a12, a13, bb.x, bb.y);
                }
            }
        }
        #pragma unroll
        for (int q = 0; q < NT; ++q) {
            xacc[q * 2]     += fmaxf(acc[0][q][0], 0.0f) + fmaxf(acc[0][q][2], 0.0f)
                             + fmaxf(acc[1][q][0], 0.0f) + fmaxf(acc[1][q][2], 0.0f);
            xacc[q * 2 + 1] += fmaxf(acc[0][q][1], 0.0f) + fmaxf(acc[0][q][3], 0.0f)
                             + fmaxf(acc[1][q][1], 0.0f) + fmaxf(acc[1][q][3], 0.0f);
        }
    }
}

__global__ __launch_bounds__(THREADS, 2)
void cosrec_kernel(
    const int*   __restrict__ seq_var,   // [512*32]
    const int*   __restrict__ user_var,  // [512]
    const int*   __restrict__ item_var,  // [512*3]
    const float* __restrict__ item_emb,  // [100000*64]
    const float* __restrict__ user_emb,  // [100000*64]
    const float* __restrict__ W2,        // [100000*164]
    const float* __restrict__ b2,        // [100000]
    const float* __restrict__ W1,        // [100*128]
    const float* __restrict__ b1,        // [100]
    const float* __restrict__ Wf2,       // [100*100]
    const float* __restrict__ bf2,       // [100]
    float*       __restrict__ out)       // [512*3]
{
    extern __shared__ char smem[];
    int*      sI     = (int*)(smem + OFF_SI);
    float*    sX     = (float*)(smem + OFF_SX);
    uint32_t* uA2    = (uint32_t*)(smem + OFF_A2);
    uint32_t* uB2    = (uint32_t*)(smem + OFF_B2);
    uint32_t* uE2    = (uint32_t*)(smem + OFF_E2);
    uint2*    bfW1   = (uint2*)(smem + OFF_W1F);
    uint2*    bfragW = (uint2*)(smem + OFF_BFRAG);

    const int row  = blockIdx.x;
    const int tid  = threadIdx.x;
    const int wid  = tid >> 5;
    const int lane = tid & 31;

    // ---- phase 0: indices ----
    if (tid < 32)       sI[tid] = seq_var[row * 32 + tid];
    else if (tid < 35)  sI[tid] = item_var[row * 3 + (tid - 32)];
    else if (tid == 35) sI[35]  = user_var[row];

    // ---- pack Wf2 b-fragments (plain [nt][ks][lane]) ----
    for (int idx = tid; idx < 13 * 7 * 32; idx += THREADS) {
        int nt  = idx / 224;
        int rem = idx - nt * 224;
        int ks  = rem >> 5, ln = rem & 31;
        int n   = nt * 8 + (ln >> 2);
        int k0  = ks * 16 + (ln & 3) * 2;
        float w0, w1, w2v, w3v;
        if (n < 100) {
            const float* wr = Wf2 + n * 100;
            w0  = (k0     < 100) ? wr[k0]     : ((k0     == 100) ? bf2[n] : 0.0f);
            w1  = (k0 + 1 < 100) ? wr[k0 + 1] : ((k0 + 1 == 100) ? bf2[n] : 0.0f);
            w2v = (k0 + 8 < 100) ? wr[k0 + 8] : ((k0 + 8 == 100) ? bf2[n] : 0.0f);
            w3v = (k0 + 9 < 100) ? wr[k0 + 9] : ((k0 + 9 == 100) ? bf2[n] : 0.0f);
        } else {
            w0 = w1 = w2v = w3v = 0.0f;
        }
        uint2 val;
        val.x = h2bits(__floats2half2_rn(w0, w1));
        val.y = h2bits(__floats2half2_rn(w2v, w3v));
        bfragW[idx] = val;
    }

    // ---- pack W1 b-fragments (part 0 = Wa + b1 col, 1 = Wb) ----
    for (int idx = tid; idx < 2 * 13 * 5 * 32; idx += THREADS) {
        int p   = idx / 2080;
        int rem = idx - p * 2080;
        int nt  = rem / 160;
        int r2  = rem - nt * 160;
        int ks  = r2 >> 5, ln = r2 & 31;
        int f   = nt * 8 + (ln >> 2);
        int k0  = ks * 16 + (ln & 3) * 2;
        float w[4] = {0.0f, 0.0f, 0.0f, 0.0f};
        if (f < 100) {
            const float* wr = W1 + f * 128 + p * 64;
            int kk4[4] = {k0, k0 + 1, k0 + 8, k0 + 9};
            #pragma unroll
            for (int q = 0; q < 4; ++q) {
                int k = kk4[q];
                if (k < 64)                 w[q] = wr[k];
                else if (p == 0 && k == 64) w[q] = b1[f];
            }
        }
        uint2 val;
        val.x = h2bits(__floats2half2_rn(w[0], w[1]));
        val.y = h2bits(__floats2half2_rn(w[2], w[3]));
        bfW1[((p * 13 + nt) * 5 + ks) * 32 + ln] = val;
    }

    const int gid = lane >> 2;   // row group 0..7
    const int tig = lane & 3;    // k group 0..3
    const int h   = wid >> 2;    // n-half: 0 -> nt 0-6, 1 -> nt 7-12
    const int mw  = wid & 3;     // a-quarter within half

    __syncthreads();

    // ---- phase 1: gather E as fp16 fragment table [l][pslot(d2)] ----
    for (int idx = tid; idx < 32 * 40; idx += THREADS) {
        int l = idx / 40, d2 = idx - l * 40;
        __half2 v;
        if (d2 < 32) {
            const float* ep = item_emb + (size_t)sI[l] * 64 + 2 * d2;
            v = __floats2half2_rn(ep[0], ep[1]);
        } else if (d2 == 32) {
            v = __floats2half2_rn(1.0f, 0.0f);
        } else {
            v = __float2half2_rn(0.0f);
        }
        uE2[l * TE + pslot(d2)] = h2bits(v);
    }
    // ---- init table slots kk=50..55 (bias col + zero pad) ----
    for (int idx = tid; idx < 32 * 6; idx += THREADS) {
        int c = idx / 6, j = idx - c * 6;
        int s = pslot(50 + j);
        uA2[c * TSTR + s] = (j == 0) ? 0x00003C00u : 0u;  // (1.0h, 0)
        uB2[c * TSTR + s] = 0u;
    }
    __syncthreads();

    // ---- phase 2: A/B via HMMA, fragments stored straight to tables ----
    for (int cb = wid; cb < 52; cb += 8) {
        const int mt = cb & 1;
        const int pn = cb >> 1;
        const int p  = pn / 13;
        const int nt = pn - p * 13;
        const int c0 = mt * 16 + gid;

        float acc[4];
        #pragma unroll
        for (int ks = 0; ks < 5; ++ks) {
            const int so = ks * 8 + tig * 2;
            uint2 Aa = *(const uint2*)&uE2[c0 * TE + so];
            uint2 Ab = *(const uint2*)&uE2[(c0 + 8) * TE + so];
            uint2 bb = bfW1[((p * 13 + nt) * 5 + ks) * 32 + lane];
            if (ks == 0) mma16816_init(acc, Aa.x, Ab.x, Aa.y, Ab.y, bb.x, bb.y);
            else         mma16816(acc, Aa.x, Ab.x, Aa.y, Ab.y, bb.x, bb.y);
        }
        const int kk = nt * 4 + tig;
        if (kk < 50) {
            uint32_t* tbl = p ? uB2 : uA2;
            const int s = pslot(kk);
            tbl[c0 * TSTR + s]       = h2bits(__floats2half2_rn(acc[0], acc[1]));
            tbl[(c0 + 8) * TSTR + s] = h2bits(__floats2half2_rn(acc[2], acc[3]));
        }
    }
    __syncthreads();

    // ---- mainloop: 8 a-blocks x 2 m-tiles x NT n-tiles per warp ----
    float xacc[14];
    #pragma unroll
    for (int j = 0; j < 14; ++j) xacc[j] = 0.0f;

    if (h == 0) run_mainloop<7, 0>(uA2, uB2, bfragW, mw, gid, tig, lane, xacc);
    else        run_mainloop<6, 7>(uA2, uB2, bfragW, mw, gid, tig, lane, xacc);

    // ---- reduction: shfl, then fixed-order over warps of same half ----
    #pragma unroll
    for (int j = 0; j < 14; ++j) {
        float s = xacc[j];
        s += __shfl_down_sync(0xffffffffu, s, 16);
        s += __shfl_down_sync(0xffffffffu, s, 8);
        s += __shfl_down_sync(0xffffffffu, s, 4);
        xacc[j] = s;
    }
    float* sRedW = (float*)(smem + OFF_RED);  // [8][56]
    if (lane < 4) {
        const int NTL = (h == 0) ? 7 : 6;
        for (int q = 0; q < NTL; ++q) {
            int n0 = q * 8 + lane * 2;         // lane == tig here
            sRedW[wid * 56 + n0]     = xacc[q * 2];
            sRedW[wid * 56 + n0 + 1] = xacc[q * 2 + 1];
        }
    }
    __syncthreads();
    if (tid < 100) {
        const int base = (tid < 56) ? 0 : 4;
        const int col  = (tid < 56) ? tid : tid - 56;
        float s = 0.0f;
        #pragma unroll
        for (int w = 0; w < 4; ++w) s += sRedW[(base + w) * 56 + col];
        sX[tid] = s;
    } else if (tid >= 128 && tid < 192) {
        int d = tid - 128;
        sX[100 + d] = user_emb[(size_t)sI[35] * 64 + d];
    }
    __syncthreads();

    // ---- out[row][t] = b2[item] + W2[item] . sX (one warp per t) ----
    if (wid < 3) {
        int it = sI[32 + wid];
        const float* w2p = W2 + (size_t)it * 164;
        float s = 0.0f;
        for (int j = lane; j < 164; j += 32) s = fmaf(w2p[j], sX[j], s);
        #pragma unroll
        for (int off = 16; off; off >>= 1)
            s += __shfl_down_sync(0xffffffffu, s, off);
        if (lane == 0) out[row * 3 + wid] = b2[it] + s;
    }
}

extern "C" void kernel_launch(void* const* d_in, const int* in_sizes, int n_in,
                              void* d_out, int out_size) {
    (void)in_sizes; (void)n_in; (void)out_size;
    cudaFuncSetAttribute(cosrec_kernel,
                         cudaFuncAttributeMaxDynamicSharedMemorySize, SMEM_TOTAL);
    cosrec_kernel<<<512, THREADS, SMEM_TOTAL>>>(
        (const int*)d_in[0],    // seq_var
        (const int*)d_in[1],    // user_var
        (const int*)d_in[2],    // item_var
        (const float*)d_in[3],  // item_emb
        (const float*)d_in[4],  // user_emb
        (const float*)d_in[5],  // W2
        (const float*)d_in[6],  // b2
        (const float*)d_in[7],  // W1
        (const float*)d_in[8],  // b1
        (const float*)d_in[9],  // Wf2
        (const float*)d_in[10], // bf2
        (float*)d_out);
}

// round 17
// speedup vs baseline: 1.4982x; 1.1205x over previous
#include <cuda_runtime.h>
#include <cuda_fp16.h>
#include <stdint.h>

// CosRec fused kernel — fp16 mma.sync (HMMA), round 17.
// = round 14 exactly, except the MAINLOOP accumulates in fp16
// (mma f16.f16.f16.f16): potentially 2x HMMA rate, and acc registers halved
// (56 -> 28). Phase-2 MMAs keep fp32 accumulate (outputs become operands).
// Precision estimate: D rel err ~1e-3 averages down ~32x in the 1024-term
// column sums -> net rel_err ~2.5e-4 (threshold 1e-3).

#define THREADS 256
#define TSTR 56            // table row stride (words)
#define TE   40            // E-fragment table row stride (words)

// ---- shared memory byte offsets ----
#define OFF_SI     0       // 72 ints                                  288 B
#define OFF_SX     288     // 2 x 164 floats                          1312 B
#define OFF_BFRAG  1664    // uint2 Wf2 bfrags [13][7][32] =         23296 B
#define OFF_A2     24960   // uint32 A-table [32][56] =               7168 B
#define OFF_B2     32128   // uint32 B-table [32][56] =               7168 B
#define OFF_W1F    39296   // uint2 W1 bfrags 2*13*5*32*8 =          33280 B
#define OFF_E2     72576   // uint32 E-table [32][40] =               5120 B
#define OFF_RED    77696   // fp32 sRedW [8][56] =                    1792 B
#define SMEM_TOTAL 79488

// fp32-accumulate (phase 2: outputs feed the operand tables)
__device__ __forceinline__ void mma16816(float* d, uint32_t a0, uint32_t a1,
                                         uint32_t a2, uint32_t a3,
                                         uint32_t b0, uint32_t b1) {
    asm volatile(
        "mma.sync.aligned.m16n8k16.row.col.f32.f16.f16.f32 "
        "{%0,%1,%2,%3}, {%4,%5,%6,%7}, {%8,%9}, {%0,%1,%2,%3};"
        : "+f"(d[0]), "+f"(d[1]), "+f"(d[2]), "+f"(d[3])
        : "r"(a0), "r"(a1), "r"(a2), "r"(a3), "r"(b0), "r"(b1));
}
__device__ __forceinline__ void mma16816_init(float* d, uint32_t a0, uint32_t a1,
                                              uint32_t a2, uint32_t a3,
                                              uint32_t b0, uint32_t b1) {
    asm volatile(
        "mma.sync.aligned.m16n8k16.row.col.f32.f16.f16.f32 "
        "{%0,%1,%2,%3}, {%4,%5,%6,%7}, {%8,%9}, {%10,%11,%12,%13};"
        : "=f"(d[0]), "=f"(d[1]), "=f"(d[2]), "=f"(d[3])
        : "r"(a0), "r"(a1), "r"(a2), "r"(a3), "r"(b0), "r"(b1),
          "f"(0.0f), "f"(0.0f), "f"(0.0f), "f"(0.0f));
}
// fp16-accumulate (mainloop): D/C are 2 regs of half2.
// d0 = rows gid,   cols (2*tig, 2*tig+1) within the n-tile
// d1 = rows gid+8, cols (2*tig, 2*tig+1)
__device__ __forceinline__ void mma16816h(uint32_t* d, uint32_t a0, uint32_t a1,
                                          uint32_t a2, uint32_t a3,
                                          uint32_t b0, uint32_t b1) {
    asm volatile(
        "mma.sync.aligned.m16n8k16.row.col.f16.f16.f16.f16 "
        "{%0,%1}, {%2,%3,%4,%5}, {%6,%7}, {%0,%1};"
        : "+r"(d[0]), "+r"(d[1])
        : "r"(a0), "r"(a1), "r"(a2), "r"(a3), "r"(b0), "r"(b1));
}
__device__ __forceinline__ void mma16816h_init(uint32_t* d, uint32_t a0, uint32_t a1,
                                               uint32_t a2, uint32_t a3,
                                               uint32_t b0, uint32_t b1) {
    asm volatile(
        "mma.sync.aligned.m16n8k16.row.col.f16.f16.f16.f16 "
        "{%0,%1}, {%2,%3,%4,%5}, {%6,%7}, {%8,%8};"
        : "=r"(d[0]), "=r"(d[1])
        : "r"(a0), "r"(a1), "r"(a2), "r"(a3), "r"(b0), "r"(b1), "r"(0u));
}

__device__ __forceinline__ uint32_t hbuild(uint32_t a, uint32_t b) {
    __half2 av = *reinterpret_cast<__half2*>(&a);
    __half2 bv = *reinterpret_cast<__half2*>(&b);
    __half2 r  = __hmax2(__hadd2(av, bv), __float2half2_rn(0.0f));
    return *reinterpret_cast<uint32_t*>(&r);
}
__device__ __forceinline__ uint32_t h2bits(__half2 v) {
    return *reinterpret_cast<uint32_t*>(&v);
}
__device__ __forceinline__ __half2 bits2h(uint32_t v) {
    return *reinterpret_cast<__half2*>(&v);
}
// paired slot: (k2, k2+4) adjacent -> slot = blk + (k2&3)*2 + ((k2>>2)&1)
__device__ __forceinline__ int pslot(int kk) {
    return (kk & ~7) + ((kk & 3) << 1) + ((kk >> 2) & 1);
}

// Mainloop for one warp: 8 a-blocks of 32 pairs (2 m-tiles per bfrag load),
// NT n-tiles starting at NTB. fp16 accumulate; xacc[2*NT] in fp32.
template<int NT, int NTB>
__device__ __forceinline__ void run_mainloop(
    const uint32_t* __restrict__ uA2, const uint32_t* __restrict__ uB2,
    const uint2* __restrict__ bfragW,
    int mw, int gid, int tig, int lane, float* xacc)
{
    const int cA0 = gid, cB0 = gid + 8, cA1 = gid + 16, cB1 = gid + 24;
    const __half2 z2 = __float2half2_rn(0.0f);
    for (int j = 0; j < 8; ++j) {
        const int aI = mw * 8 + j;       // 32-pair block index == a index
        uint32_t acc[2][NT][2];
        #pragma unroll
        for (int ks = 0; ks < 7; ++ks) {
            const int so = ks * 8 + tig * 2;
            uint2 Bab = *(const uint2*)&uB2[aI  * TSTR + so];
            uint2 Aa0 = *(const uint2*)&uA2[cA0 * TSTR + so];
            uint2 Ab0 = *(const uint2*)&uA2[cB0 * TSTR + so];
            uint2 Aa1 = *(const uint2*)&uA2[cA1 * TSTR + so];
            uint2 Ab1 = *(const uint2*)&uA2[cB1 * TSTR + so];
            uint32_t a00 = hbuild(Aa0.x, Bab.x), a01 = hbuild(Ab0.x, Bab.x);
            uint32_t a02 = hbuild(Aa0.y, Bab.y), a03 = hbuild(Ab0.y, Bab.y);
            uint32_t a10 = hbuild(Aa1.x, Bab.x), a11 = hbuild(Ab1.x, Bab.x);
            uint32_t a12 = hbuild(Aa1.y, Bab.y), a13 = hbuild(Ab1.y, Bab.y);
            #pragma unroll
            for (int q = 0; q < NT; ++q) {
                uint2 bb = bfragW[((NTB + q) * 7 + ks) * 32 + lane];
                if (ks == 0) {
                    mma16816h_init(acc[0][q], a00, a01, a02, a03, bb.x, bb.y);
                    mma16816h_init(acc[1][q], a10, a11, a12, a13, bb.x, bb.y);
                } else {
                    mma16816h(acc[0][q], a00, a01, a02, a03, bb.x, bb.y);
                    mma16816h(acc[1][q], a10, a11, a12, a13, bb.x, bb.y);
                }
            }
        }
        #pragma unroll
        for (int q = 0; q < NT; ++q) {
            // relu per element, pairwise half add (one rounding), then fp32.
            __half2 s0 = __hadd2(__hmax2(bits2h(acc[0][q][0]), z2),
                                 __hmax2(bits2h(acc[0][q][1]), z2));
            __half2 s1 = __hadd2(__hmax2(bits2h(acc[1][q][0]), z2),
                                 __hmax2(bits2h(acc[1][q][1]), z2));
            float2 f0 = __half22float2(s0);
            float2 f1 = __half22float2(s1);
            xacc[q * 2]     += f0.x + f1.x;
            xacc[q * 2 + 1] += f0.y + f1.y;
        }
    }
}

__global__ __launch_bounds__(THREADS, 2)
void cosrec_kernel(
    const int*   __restrict__ seq_var,   // [512*32]
    const int*   __restrict__ user_var,  // [512]
    const int*   __restrict__ item_var,  // [512*3]
    const float* __restrict__ item_emb,  // [100000*64]
    const float* __restrict__ user_emb,  // [100000*64]
    const float* __restrict__ W2,        // [100000*164]
    const float* __restrict__ b2,        // [100000]
    const float* __restrict__ W1,        // [100*128]
    const float* __restrict__ b1,        // [100]
    const float* __restrict__ Wf2,       // [100*100]
    const float* __restrict__ bf2,       // [100]
    float*       __restrict__ out)       // [512*3]
{
    extern __shared__ char smem[];
    int*      sI     = (int*)(smem + OFF_SI);
    float*    sX     = (float*)(smem + OFF_SX);     // [2][164]
    uint32_t* uA2    = (uint32_t*)(smem + OFF_A2);
    uint32_t* uB2    = (uint32_t*)(smem + OFF_B2);
    uint32_t* uE2    = (uint32_t*)(smem + OFF_E2);
    uint2*    bfW1   = (uint2*)(smem + OFF_W1F);
    uint2*    bfragW = (uint2*)(smem + OFF_BFRAG);

    const int row0 = blockIdx.x * 2;
    const int row1 = row0 + 1;
    const int tid  = threadIdx.x;
    const int wid  = tid >> 5;
    const int lane = tid & 31;

    // ---- phase 0: indices for both rows ----
    if (tid < 32)       sI[tid]            = seq_var[row0 * 32 + tid];
    else if (tid < 64)  sI[36 + tid - 32]  = seq_var[row1 * 32 + (tid - 32)];
    else if (tid < 67)  sI[32 + tid - 64]  = item_var[row0 * 3 + (tid - 64)];
    else if (tid < 70)  sI[68 + tid - 67]  = item_var[row1 * 3 + (tid - 67)];
    else if (tid == 70) sI[35]             = user_var[row0];
    else if (tid == 71) sI[71]             = user_var[row1];

    // ---- phase B1: pack Wf2 b-fragments ONCE (plain [nt][ks][lane]) ----
    for (int idx = tid; idx < 13 * 7 * 32; idx += THREADS) {
        int nt  = idx / 224;
        int rem = idx - nt * 224;
        int ks  = rem >> 5, ln = rem & 31;
        int n   = nt * 8 + (ln >> 2);
        int k0  = ks * 16 + (ln & 3) * 2;
        float w0, w1, w2v, w3v;
        if (n < 100) {
            const float* wr = Wf2 + n * 100;
            w0  = (k0     < 100) ? wr[k0]     : ((k0     == 100) ? bf2[n] : 0.0f);
            w1  = (k0 + 1 < 100) ? wr[k0 + 1] : ((k0 + 1 == 100) ? bf2[n] : 0.0f);
            w2v = (k0 + 8 < 100) ? wr[k0 + 8] : ((k0 + 8 == 100) ? bf2[n] : 0.0f);
            w3v = (k0 + 9 < 100) ? wr[k0 + 9] : ((k0 + 9 == 100) ? bf2[n] : 0.0f);
        } else {
            w0 = w1 = w2v = w3v = 0.0f;
        }
        uint2 val;
        val.x = h2bits(__floats2half2_rn(w0, w1));
        val.y = h2bits(__floats2half2_rn(w2v, w3v));
        bfragW[idx] = val;
    }

    // ---- phase B2: pack W1 b-fragments ONCE (part 0 = Wa + b1 col, 1 = Wb) ----
    for (int idx = tid; idx < 2 * 13 * 5 * 32; idx += THREADS) {
        int p   = idx / 2080;
        int rem = idx - p * 2080;
        int nt  = rem / 160;
        int r2  = rem - nt * 160;
        int ks  = r2 >> 5, ln = r2 & 31;
        int f   = nt * 8 + (ln >> 2);
        int k0  = ks * 16 + (ln & 3) * 2;
        float w[4] = {0.0f, 0.0f, 0.0f, 0.0f};
        if (f < 100) {
            const float* wr = W1 + f * 128 + p * 64;
            int kk4[4] = {k0, k0 + 1, k0 + 8, k0 + 9};
            #pragma unroll
            for (int q = 0; q < 4; ++q) {
                int k = kk4[q];
                if (k < 64)                 w[q] = wr[k];
                else if (p == 0 && k == 64) w[q] = b1[f];
            }
        }
        uint2 val;
        val.x = h2bits(__floats2half2_rn(w[0], w[1]));
        val.y = h2bits(__floats2half2_rn(w[2], w[3]));
        bfW1[((p * 13 + nt) * 5 + ks) * 32 + ln] = val;
    }

    const int gid = lane >> 2;   // row group 0..7
    const int tig = lane & 3;    // k group 0..3
    const int h   = wid >> 2;    // n-half: 0 -> nt 0-6, 1 -> nt 7-12
    const int mw  = wid & 3;     // a-quarter within half

    // ==== per-batch-row loop ====
    for (int r = 0; r < 2; ++r) {
        const int ib = r * 36;
        __syncthreads();

        // ---- phase 1: gather E as fp16 fragment table [l][pslot(d2)] ----
        for (int idx = tid; idx < 32 * 40; idx += THREADS) {
            int l = idx / 40, d2 = idx - l * 40;
            __half2 v;
            if (d2 < 32) {
                const float* ep = item_emb + (size_t)sI[ib + l] * 64 + 2 * d2;
                v = __floats2half2_rn(ep[0], ep[1]);
            } else if (d2 == 32) {
                v = __floats2half2_rn(1.0f, 0.0f);
            } else {
                v = __float2half2_rn(0.0f);
            }
            uE2[l * TE + pslot(d2)] = h2bits(v);
        }
        // ---- init table slots kk=50..55 (bias col + zero pad) ----
        for (int idx = tid; idx < 32 * 6; idx += THREADS) {
            int c = idx / 6, j = idx - c * 6;
            int s = pslot(50 + j);
            uA2[c * TSTR + s] = (j == 0) ? 0x00003C00u : 0u;  // (1.0h, 0)
            uB2[c * TSTR + s] = 0u;
        }
        __syncthreads();

        // ---- phase 2: A/B via HMMA (fp32 acc), stored straight to tables ----
        for (int cb = wid; cb < 52; cb += 8) {
            const int mt = cb & 1;
            const int pn = cb >> 1;
            const int p  = pn / 13;
            const int nt = pn - p * 13;
            const int c0 = mt * 16 + gid;

            float acc[4];
            #pragma unroll
            for (int ks = 0; ks < 5; ++ks) {
                const int so = ks * 8 + tig * 2;
                uint2 Aa = *(const uint2*)&uE2[c0 * TE + so];
                uint2 Ab = *(const uint2*)&uE2[(c0 + 8) * TE + so];
                uint2 bb = bfW1[((p * 13 + nt) * 5 + ks) * 32 + lane];
                if (ks == 0) mma16816_init(acc, Aa.x, Ab.x, Aa.y, Ab.y, bb.x, bb.y);
                else         mma16816(acc, Aa.x, Ab.x, Aa.y, Ab.y, bb.x, bb.y);
            }
            const int kk = nt * 4 + tig;
            if (kk < 50) {
                uint32_t* tbl = p ? uB2 : uA2;
                const int s = pslot(kk);
                tbl[c0 * TSTR + s]       = h2bits(__floats2half2_rn(acc[0], acc[1]));
                tbl[(c0 + 8) * TSTR + s] = h2bits(__floats2half2_rn(acc[2], acc[3]));
            }
        }
        __syncthreads();

        // ---- mainloop: 8 a-blocks x 2 m-tiles x NT n-tiles, fp16 acc ----
        float xacc[14];
        #pragma unroll
        for (int j = 0; j < 14; ++j) xacc[j] = 0.0f;

        if (h == 0) run_mainloop<7, 0>(uA2, uB2, bfragW, mw, gid, tig, lane, xacc);
        else        run_mainloop<6, 7>(uA2, uB2, bfragW, mw, gid, tig, lane, xacc);

        // ---- reduction: shfl, then fixed-order over warps of same half ----
        #pragma unroll
        for (int j = 0; j < 14; ++j) {
            float s = xacc[j];
            s += __shfl_down_sync(0xffffffffu, s, 16);
            s += __shfl_down_sync(0xffffffffu, s, 8);
            s += __shfl_down_sync(0xffffffffu, s, 4);
            xacc[j] = s;
        }
        float* sRedW = (float*)(smem + OFF_RED);  // [8][56]
        if (lane < 4) {
            const int NTL = (h == 0) ? 7 : 6;
            for (int q = 0; q < NTL; ++q) {
                int n0 = q * 8 + lane * 2;         // lane == tig here
                sRedW[wid * 56 + n0]     = xacc[q * 2];
                sRedW[wid * 56 + n0 + 1] = xacc[q * 2 + 1];
            }
        }
        __syncthreads();
        if (tid < 100) {
            const int base = (tid < 56) ? 0 : 4;
            const int col  = (tid < 56) ? tid : tid - 56;
            float s = 0.0f;
            #pragma unroll
            for (int w = 0; w < 4; ++w) s += sRedW[(base + w) * 56 + col];
            sX[r * 164 + tid] = s;
        } else if (tid >= 128 && tid < 192) {
            int d = tid - 128;
            sX[r * 164 + 100 + d] = user_emb[(size_t)sI[ib + 35] * 64 + d];
        }
    }
    __syncthreads();

    // ---- out[row][t] = b2[item] + W2[item] . sX[r]  (one warp per output) ----
    if (wid < 6) {
        int r  = wid / 3, t = wid - r * 3;
        int it = sI[r * 36 + 32 + t];
        const float* w2p = W2 + (size_t)it * 164;
        const float* xp  = sX + r * 164;
        float s = 0.0f;
        for (int j = lane; j < 164; j += 32) s = fmaf(w2p[j], xp[j], s);
        #pragma unroll
        for (int off = 16; off; off >>= 1)
            s += __shfl_down_sync(0xffffffffu, s, off);
        if (lane == 0) out[(row0 + r) * 3 + t] = b2[it] + s;
    }
}

extern "C" void kernel_launch(void* const* d_in, const int* in_sizes, int n_in,
                              void* d_out, int out_size) {
    (void)in_sizes; (void)n_in; (void)out_size;
    cudaFuncSetAttribute(cosrec_kernel,
                         cudaFuncAttributeMaxDynamicSharedMemorySize, SMEM_TOTAL);
    cosrec_kernel<<<256, THREADS, SMEM_TOTAL>>>(
        (const int*)d_in[0],    // seq_var
        (const int*)d_in[1],    // user_var
        (const int*)d_in[2],    // item_var
        (const float*)d_in[3],  // item_emb
        (const float*)d_in[4],  // user_emb
        (const float*)d_in[5],  // W2
        (const float*)d_in[6],  // b2
        (const float*)d_in[7],  // W1
        (const float*)d_in[8],  // b1
        (const float*)d_in[9],  // Wf2
        (const float*)d_in[10], // bf2
        (float*)d_out);
}